// round 4
// baseline (speedup 1.0000x reference)
#include <cuda_runtime.h>
#include <cstdint>

#define DI __device__ __forceinline__

static constexpr int HDIM   = 1024;
static constexpr int BATCH  = 8192;
static constexpr int BM     = 128;   // batch rows per CTA
static constexpr int BN     = 32;    // gate cols per CTA (x6 gate blocks)
static constexpr int NTH    = 512;   // 16 warps: 4 (m) x 4 (n)
static constexpr int NSTAGE = 96;    // 32 input + 32 hx + 32 att K-stages

// stage buffer: A 128x32 tf32 (16KB) + B 4x32x32 (16KB), 4-deep ring
static constexpr int ABYTES = BM * 128;        // 16384
static constexpr int BUFB   = ABYTES + 16384;  // 32768
static constexpr int SMEMB  = 4 * BUFB;        // 131072

// tf32-converted scratch (prepass output). Offsets in u32 elements.
static constexpr size_t OFF_INP  = 0;
static constexpr size_t OFF_HX   = 8388608;
static constexpr size_t OFF_ATT  = 16777216;
static constexpr size_t OFF_WIH  = 25165824;
static constexpr size_t OFF_WHH  = 29360128;
static constexpr size_t OFF_WATT = 33554432;
static constexpr size_t CVT_TOTAL = 35651584;   // ~142.6 MB

__device__ uint32_t g_cvt[CVT_TOTAL];

DI uint32_t f2tf(float x) {  // round-to-nearest tf32 (unbiased)
    uint32_t r;
    asm("cvt.rna.tf32.f32 %0, %1;" : "=r"(r) : "f"(x));
    return r;
}
DI float sigmf(float x) { return 1.0f / (1.0f + __expf(-x)); }

DI uint32_t smem_u32(const void* p) {
    uint32_t r;
    asm("{ .reg .u64 t; cvta.to.shared.u64 t, %1; cvt.u32.u64 %0, t; }" : "=r"(r) : "l"(p));
    return r;
}
DI void cp16(uint32_t sdst, const uint32_t* gsrc) {
    asm volatile("cp.async.cg.shared.global [%0], [%1], 16;" :: "r"(sdst), "l"(gsrc));
}
DI void cp_commit() { asm volatile("cp.async.commit_group;" ::: "memory"); }
template <int N>
DI void cp_wait() { asm volatile("cp.async.wait_group %0;" :: "n"(N) : "memory"); }

DI void ldsm4(uint32_t* r, uint32_t addr) {
    asm volatile("ldmatrix.sync.aligned.m8n8.x4.shared.b16 {%0,%1,%2,%3}, [%4];"
                 : "=r"(r[0]), "=r"(r[1]), "=r"(r[2]), "=r"(r[3]) : "r"(addr));
}
DI void ldsm2(uint32_t* r, uint32_t addr) {
    asm volatile("ldmatrix.sync.aligned.m8n8.x2.shared.b16 {%0,%1}, [%2];"
                 : "=r"(r[0]), "=r"(r[1]) : "r"(addr));
}
DI void mma8(float* d, const uint32_t* a, const uint32_t* b) {
    asm volatile(
        "mma.sync.aligned.m16n8k8.row.col.f32.tf32.tf32.f32 "
        "{%0,%1,%2,%3}, {%4,%5,%6,%7}, {%8,%9}, {%0,%1,%2,%3};"
        : "+f"(d[0]), "+f"(d[1]), "+f"(d[2]), "+f"(d[3])
        : "r"(a[0]), "r"(a[1]), "r"(a[2]), "r"(a[3]), "r"(b[0]), "r"(b[1]));
}

// ---- prepass: single launch, fp32 -> tf32(RNA) bulk convert (6 segments) ----
__global__ void cvt_all_kernel(const float4* s0, const float4* s1, const float4* s2,
                               const float4* s3, const float4* s4, const float4* s5)
{
    const int seg = blockIdx.y;
    const float4* src;
    uint4* dst;
    int n4;
    uint32_t* g = g_cvt;
    switch (seg) {
        case 0: src = s0; dst = (uint4*)(g + OFF_INP);  n4 = 2097152; break;
        case 1: src = s1; dst = (uint4*)(g + OFF_HX);   n4 = 2097152; break;
        case 2: src = s2; dst = (uint4*)(g + OFF_ATT);  n4 = 2097152; break;
        case 3: src = s3; dst = (uint4*)(g + OFF_WIH);  n4 = 1048576; break;
        case 4: src = s4; dst = (uint4*)(g + OFF_WHH);  n4 = 1048576; break;
        default: src = s5; dst = (uint4*)(g + OFF_WATT); n4 = 524288; break;
    }
    int i = blockIdx.x * blockDim.x + threadIdx.x;
    int stride = gridDim.x * blockDim.x;
    for (; i < n4; i += stride) {
        float4 v = __ldg(src + i);
        dst[i] = make_uint4(f2tf(v.x), f2tf(v.y), f2tf(v.z), f2tf(v.w));
    }
}

// ---- main kernel ----
// stages 0..31 : A=input, B=wih  (4 gate blocks, accum c[0..3])
// stages 32..63: A=hx,    B=whh  (4 gate blocks, accum c[0..3])
// stages 64..95: A=att,   B=watt (2 att blocks,  accum c[4..5])
DI void issue_stage(int s, int m0, int n0, int tid, uint32_t sbase) {
    int seg = s >> 5;
    int k0  = (s & 31) << 5;
    int nb  = (seg == 2) ? 2 : 4;
    const uint32_t* Ag;
    const uint32_t* Bg;
    if (seg == 0)      { Ag = g_cvt + OFF_INP; Bg = g_cvt + OFF_WIH;  }
    else if (seg == 1) { Ag = g_cvt + OFF_HX;  Bg = g_cvt + OFF_WHH;  }
    else               { Ag = g_cvt + OFF_ATT; Bg = g_cvt + OFF_WATT; }
    const uint32_t buf = sbase + (s & 3) * BUFB;
    #pragma unroll
    for (int j = 0; j < 2; ++j) {               // A: 1024 16B chunks
        int idx = tid + j * NTH;
        int r = idx >> 3, cc = idx & 7;
        uint32_t sdst = buf + r * 128 + ((cc ^ (r & 7)) << 4);
        cp16(sdst, Ag + (size_t)(m0 + r) * HDIM + k0 + cc * 4);
    }
    #pragma unroll
    for (int j = 0; j < 2; ++j) {               // B: nb x 256 chunks
        int idx = tid + j * NTH;
        int blk = idx >> 8, rem = idx & 255;
        if (blk < nb) {
            int r = rem >> 3, cc = rem & 7;
            uint32_t sdst = buf + ABYTES + blk * 4096 + r * 128 + ((cc ^ (r & 7)) << 4);
            cp16(sdst, Bg + (size_t)(blk * HDIM + n0 + r) * HDIM + k0 + cc * 4);
        }
    }
    cp_commit();
}

template <int NB, int CB>
DI void compute_stage(uint32_t sbuf, int wm, int wn, int lane, float c[6][2][4]) {
    const uint32_t Ab = sbuf;
    const uint32_t Bb = sbuf + ABYTES;
    // A: rows wm*32 + [0,32); two 16-row fragments via ldmatrix.x4
    const int rowA  = wm * 32 + (lane & 15);
    const int ahi   = (lane >> 4) & 1;
    const uint32_t aoff0 = Ab + rowA * 128;
    const uint32_t aoff1 = Ab + (rowA + 16) * 128;
    const int ax = rowA & 7;                  // (rowA+16)&7 == ax
    // B: rows wn*8 + [0,8); one 8-row fragment via ldmatrix.x2 (lanes 0-15 supply addrs)
    const int l16  = lane & 15;
    const int rowB = wn * 8 + (l16 & 7);
    const int bhi  = (l16 >> 3) & 1;
    const uint32_t boff = rowB * 128;
    const int bx = rowB & 7;
    #pragma unroll
    for (int k8 = 0; k8 < 4; ++k8) {
        uint32_t a0[4], a1[4];
        const int ca = k8 * 2 + ahi;
        ldsm4(a0, aoff0 + ((ca ^ ax) << 4));
        ldsm4(a1, aoff1 + ((ca ^ ax) << 4));
        const int cb = k8 * 2 + bhi;
        #pragma unroll
        for (int blk = 0; blk < NB; ++blk) {
            uint32_t b[2];
            ldsm2(b, Bb + blk * 4096 + boff + ((cb ^ bx) << 4));
            mma8(c[CB + blk][0], a0, b);
            mma8(c[CB + blk][1], a1, b);
        }
    }
}

__global__ __launch_bounds__(NTH, 1)
void lstm_att_kernel(const float* __restrict__ cx,
                     const float* __restrict__ bih, const float* __restrict__ bhh,
                     const float* __restrict__ batt,
                     float* __restrict__ out)
{
    extern __shared__ char smem[];
    const int tid  = threadIdx.x;
    const int wid  = tid >> 5;
    const int lane = tid & 31;
    const int wm = wid >> 2, wn = wid & 3;    // 4 x 4 warp grid
    const int n0 = blockIdx.x * BN;
    const int m0 = blockIdx.y * BM;
    const uint32_t sbase = smem_u32(smem);

    float c[6][2][4];
    #pragma unroll
    for (int b = 0; b < 6; ++b)
        #pragma unroll
        for (int mf = 0; mf < 2; ++mf)
            #pragma unroll
            for (int i = 0; i < 4; ++i) c[b][mf][i] = 0.0f;

    issue_stage(0, m0, n0, tid, sbase);
    issue_stage(1, m0, n0, tid, sbase);
    issue_stage(2, m0, n0, tid, sbase);

    for (int s = 0; s < NSTAGE; ++s) {
        cp_wait<2>();
        __syncthreads();
        if (s + 3 < NSTAGE) issue_stage(s + 3, m0, n0, tid, sbase);
        const uint32_t buf = sbase + (s & 3) * BUFB;
        if (s < 64) compute_stage<4, 0>(buf, wm, wn, lane, c);
        else        compute_stage<2, 4>(buf, wm, wn, lane, c);
    }

    // ---- fused LSTM epilogue: all 6 gates for (row,col) live in this thread ----
    const int gid = lane >> 2, tig = lane & 3;
    const size_t cy_base = (size_t)BATCH * HDIM;
    const int col = n0 + wn * 8 + tig * 2;
    #pragma unroll
    for (int mf = 0; mf < 2; ++mf) {
        #pragma unroll
        for (int i2 = 0; i2 < 2; ++i2) {
            const int row = m0 + wm * 32 + mf * 16 + gid + i2 * 8;
            float2 cx2 = __ldg((const float2*)(cx + (size_t)row * HDIM + col));
            float hyv[2], cyv[2];
            #pragma unroll
            for (int q = 0; q < 2; ++q) {
                const int i = i2 * 2 + q;
                const int n = col + q;
                float gi  = c[0][mf][i] + __ldg(bih + n)        + __ldg(bhh + n);
                float gf  = c[1][mf][i] + __ldg(bih + 1024 + n) + __ldg(bhh + 1024 + n);
                float gc  = c[2][mf][i] + __ldg(bih + 2048 + n) + __ldg(bhh + 2048 + n);
                float go  = c[3][mf][i] + __ldg(bih + 3072 + n) + __ldg(bhh + 3072 + n);
                float gia = c[4][mf][i] + __ldg(batt + n);
                float gaa = c[5][mf][i] + __ldg(batt + 1024 + n);
                float i_  = sigmf(gi);
                float f_  = sigmf(gf);
                float c_  = tanhf(gc);
                float o_  = sigmf(go);
                float ia_ = sigmf(gia);
                float aa_ = tanhf(gaa);
                float cv  = f_ * ((q == 0) ? cx2.x : cx2.y) + i_ * c_ + ia_ * aa_;
                cyv[q] = cv;
                hyv[q] = o_ * tanhf(cv);
            }
            *(float2*)(out + (size_t)row * HDIM + col)           = make_float2(hyv[0], hyv[1]);
            *(float2*)(out + cy_base + (size_t)row * HDIM + col) = make_float2(cyv[0], cyv[1]);
        }
    }
}

extern "C" void kernel_launch(void* const* d_in, const int* in_sizes, int n_in,
                              void* d_out, int out_size)
{
    (void)in_sizes; (void)n_in; (void)out_size;
    const float* inp  = (const float*)d_in[0];
    const float* hx   = (const float*)d_in[1];
    const float* cx   = (const float*)d_in[2];
    const float* att  = (const float*)d_in[3];
    const float* wih  = (const float*)d_in[4];
    const float* whh  = (const float*)d_in[5];
    const float* bih  = (const float*)d_in[6];
    const float* bhh  = (const float*)d_in[7];
    const float* watt = (const float*)d_in[8];
    const float* batt = (const float*)d_in[9];
    float* out = (float*)d_out;

    dim3 cgrid(1024, 6);
    cvt_all_kernel<<<cgrid, 256>>>((const float4*)inp, (const float4*)hx,
                                   (const float4*)att, (const float4*)wih,
                                   (const float4*)whh, (const float4*)watt);

    cudaFuncSetAttribute(lstm_att_kernel,
                         cudaFuncAttributeMaxDynamicSharedMemorySize, SMEMB);
    dim3 grid(HDIM / BN, BATCH / BM);  // n-tiles fastest => A/L2 reuse within a wave
    lstm_att_kernel<<<grid, NTH, SMEMB>>>(cx, bih, bhh, batt, out);
}

// round 5
// speedup vs baseline: 1.3114x; 1.3114x over previous
#include <cuda_runtime.h>
#include <cstdint>

#define DI __device__ __forceinline__

static constexpr int HDIM   = 1024;
static constexpr int BATCH  = 8192;
static constexpr int BM     = 128;   // batch rows per CTA
static constexpr int BN     = 32;    // gate cols per CTA (x6 gate blocks)
static constexpr int NTH    = 256;   // 8 warps: 4 (m) x 2 (n)
static constexpr int NSTAGE = 96;    // 32 input + 32 hx + 32 att K-stages
static constexpr int RING   = 3;     // 3-deep ring -> 96KB -> 2 CTAs/SM

// stage buffer: A 128x32 tf32 (16KB) + B 4x32x32 (16KB)
static constexpr int ABYTES = BM * 128;        // 16384
static constexpr int BUFB   = ABYTES + 16384;  // 32768
static constexpr int SMEMB  = RING * BUFB;     // 98304

// tf32-converted scratch (prepass output). Offsets in u32 elements.
static constexpr size_t OFF_INP  = 0;
static constexpr size_t OFF_HX   = 8388608;
static constexpr size_t OFF_ATT  = 16777216;
static constexpr size_t OFF_WIH  = 25165824;
static constexpr size_t OFF_WHH  = 29360128;
static constexpr size_t OFF_WATT = 33554432;
static constexpr size_t CVT_TOTAL = 35651584;   // ~142.6 MB

__device__ uint32_t g_cvt[CVT_TOTAL];

DI uint32_t f2tf(float x) {  // round-to-nearest tf32 (unbiased)
    uint32_t r;
    asm("cvt.rna.tf32.f32 %0, %1;" : "=r"(r) : "f"(x));
    return r;
}
DI float sigmf(float x) { return 1.0f / (1.0f + __expf(-x)); }

DI uint32_t smem_u32(const void* p) {
    uint32_t r;
    asm("{ .reg .u64 t; cvta.to.shared.u64 t, %1; cvt.u32.u64 %0, t; }" : "=r"(r) : "l"(p));
    return r;
}
DI void cp16(uint32_t sdst, const uint32_t* gsrc) {
    asm volatile("cp.async.cg.shared.global [%0], [%1], 16;" :: "r"(sdst), "l"(gsrc));
}
DI void cp_commit() { asm volatile("cp.async.commit_group;" ::: "memory"); }
template <int N>
DI void cp_wait() { asm volatile("cp.async.wait_group %0;" :: "n"(N) : "memory"); }

DI void ldsm4(uint32_t* r, uint32_t addr) {
    asm volatile("ldmatrix.sync.aligned.m8n8.x4.shared.b16 {%0,%1,%2,%3}, [%4];"
                 : "=r"(r[0]), "=r"(r[1]), "=r"(r[2]), "=r"(r[3]) : "r"(addr));
}
DI void mma8(float* d, const uint32_t* a, const uint32_t* b) {
    asm volatile(
        "mma.sync.aligned.m16n8k8.row.col.f32.tf32.tf32.f32 "
        "{%0,%1,%2,%3}, {%4,%5,%6,%7}, {%8,%9}, {%0,%1,%2,%3};"
        : "+f"(d[0]), "+f"(d[1]), "+f"(d[2]), "+f"(d[3])
        : "r"(a[0]), "r"(a[1]), "r"(a[2]), "r"(a[3]), "r"(b[0]), "r"(b[1]));
}

// ---- prepass: single launch, fp32 -> tf32(RNA) bulk convert (6 segments) ----
__global__ void cvt_all_kernel(const float4* s0, const float4* s1, const float4* s2,
                               const float4* s3, const float4* s4, const float4* s5)
{
    const int seg = blockIdx.y;
    const float4* src;
    uint4* dst;
    int n4;
    uint32_t* g = g_cvt;
    switch (seg) {
        case 0: src = s0; dst = (uint4*)(g + OFF_INP);  n4 = 2097152; break;
        case 1: src = s1; dst = (uint4*)(g + OFF_HX);   n4 = 2097152; break;
        case 2: src = s2; dst = (uint4*)(g + OFF_ATT);  n4 = 2097152; break;
        case 3: src = s3; dst = (uint4*)(g + OFF_WIH);  n4 = 1048576; break;
        case 4: src = s4; dst = (uint4*)(g + OFF_WHH);  n4 = 1048576; break;
        default: src = s5; dst = (uint4*)(g + OFF_WATT); n4 = 524288; break;
    }
    int i = blockIdx.x * blockDim.x + threadIdx.x;
    int stride = gridDim.x * blockDim.x;
    for (; i < n4; i += stride) {
        float4 v = __ldg(src + i);
        dst[i] = make_uint4(f2tf(v.x), f2tf(v.y), f2tf(v.z), f2tf(v.w));
    }
}

// ---- main kernel ----
// stages 0..31 : A=input, B=wih  (4 gate blocks, accum c[0..3])
// stages 32..63: A=hx,    B=whh  (4 gate blocks, accum c[0..3])
// stages 64..95: A=att,   B=watt (2 att blocks,  accum c[4..5])
DI void issue_stage(int s, int m0, int n0, int tid, uint32_t sbase) {
    int seg = s >> 5;
    int k0  = (s & 31) << 5;
    int nb  = (seg == 2) ? 2 : 4;
    const uint32_t* Ag;
    const uint32_t* Bg;
    if (seg == 0)      { Ag = g_cvt + OFF_INP; Bg = g_cvt + OFF_WIH;  }
    else if (seg == 1) { Ag = g_cvt + OFF_HX;  Bg = g_cvt + OFF_WHH;  }
    else               { Ag = g_cvt + OFF_ATT; Bg = g_cvt + OFF_WATT; }
    const int ring = s % RING;
    const uint32_t buf = sbase + ring * BUFB;
    #pragma unroll
    for (int j = 0; j < 4; ++j) {               // A: 1024 16B chunks
        int idx = tid + j * NTH;
        int r = idx >> 3, cc = idx & 7;
        uint32_t sdst = buf + r * 128 + ((cc ^ (r & 7)) << 4);
        cp16(sdst, Ag + (size_t)(m0 + r) * HDIM + k0 + cc * 4);
    }
    #pragma unroll
    for (int j = 0; j < 4; ++j) {               // B: nb x 256 chunks
        if (j < 2 || nb == 4) {
            int idx = tid + j * NTH;
            int blk = idx >> 8, rem = idx & 255;
            int r = rem >> 3, cc = rem & 7;
            uint32_t sdst = buf + ABYTES + blk * 4096 + r * 128 + ((cc ^ (r & 7)) << 4);
            cp16(sdst, Bg + (size_t)(blk * HDIM + n0 + r) * HDIM + k0 + cc * 4);
        }
    }
    cp_commit();
}

template <int NB, int CB>
DI void compute_stage(uint32_t sbuf, int wm, int wn, int lane, float c[6][2][2][4]) {
    const uint32_t Ab = sbuf;
    const uint32_t Bb = sbuf + ABYTES;
    // A: rows wm*32 + [0,32); two 16-row fragments via ldmatrix.x4
    const int rowA  = wm * 32 + (lane & 15);
    const int ahi   = (lane >> 4) & 1;
    const uint32_t aoff0 = Ab + rowA * 128;
    const uint32_t aoff1 = Ab + (rowA + 16) * 128;
    const int ax = rowA & 7;                  // (rowA+16)&7 == ax
    // B: rows wn*16 + [0,16); one 16-row fragment (2 n-frags) via ldmatrix.x4
    const int rowB = wn * 16 + (lane & 7) + ((lane & 16) >> 1);
    const int bhi  = (lane >> 3) & 1;
    const uint32_t boff = rowB * 128;
    const int bx = rowB & 7;
    #pragma unroll
    for (int k8 = 0; k8 < 4; ++k8) {
        uint32_t a0[4], a1[4];
        const int ca = k8 * 2 + ahi;
        ldsm4(a0, aoff0 + ((ca ^ ax) << 4));
        ldsm4(a1, aoff1 + ((ca ^ ax) << 4));
        const int cb = k8 * 2 + bhi;
        #pragma unroll
        for (int blk = 0; blk < NB; ++blk) {
            uint32_t b[4];
            ldsm4(b, Bb + blk * 4096 + boff + ((cb ^ bx) << 4));
            mma8(c[CB + blk][0][0], a0, b);
            mma8(c[CB + blk][0][1], a0, b + 2);
            mma8(c[CB + blk][1][0], a1, b);
            mma8(c[CB + blk][1][1], a1, b + 2);
        }
    }
}

__global__ __launch_bounds__(NTH, 2)
void lstm_att_kernel(const float* __restrict__ cx,
                     const float* __restrict__ bih, const float* __restrict__ bhh,
                     const float* __restrict__ batt,
                     float* __restrict__ out)
{
    extern __shared__ char smem[];
    const int tid  = threadIdx.x;
    const int wid  = tid >> 5;
    const int lane = tid & 31;
    const int wm = wid >> 1, wn = wid & 1;
    const int n0 = blockIdx.x * BN;
    const int m0 = blockIdx.y * BM;
    const uint32_t sbase = smem_u32(smem);

    float c[6][2][2][4];
    #pragma unroll
    for (int b = 0; b < 6; ++b)
        #pragma unroll
        for (int mf = 0; mf < 2; ++mf)
            #pragma unroll
            for (int nf = 0; nf < 2; ++nf)
                #pragma unroll
                for (int i = 0; i < 4; ++i) c[b][mf][nf][i] = 0.0f;

    issue_stage(0, m0, n0, tid, sbase);
    issue_stage(1, m0, n0, tid, sbase);

    for (int s = 0; s < NSTAGE; ++s) {
        cp_wait<1>();
        __syncthreads();
        if (s + 2 < NSTAGE) issue_stage(s + 2, m0, n0, tid, sbase);
        const uint32_t buf = sbase + (s % RING) * BUFB;
        if (s < 64) compute_stage<4, 0>(buf, wm, wn, lane, c);
        else        compute_stage<2, 4>(buf, wm, wn, lane, c);
        __syncthreads();
    }

    // ---- fused LSTM epilogue: all 6 gates for (row,col) live in this thread ----
    const int gid = lane >> 2, tig = lane & 3;
    const size_t cy_base = (size_t)BATCH * HDIM;
    #pragma unroll
    for (int mf = 0; mf < 2; ++mf) {
        #pragma unroll
        for (int i2 = 0; i2 < 2; ++i2) {
            const int row = m0 + wm * 32 + mf * 16 + gid + i2 * 8;
            #pragma unroll
            for (int nf = 0; nf < 2; ++nf) {
                const int col = n0 + wn * 16 + nf * 8 + tig * 2;
                float2 cx2 = __ldg((const float2*)(cx + (size_t)row * HDIM + col));
                float hyv[2], cyv[2];
                #pragma unroll
                for (int q = 0; q < 2; ++q) {
                    const int i = i2 * 2 + q;
                    const int n = col + q;
                    float gi  = c[0][mf][nf][i] + __ldg(bih + n)        + __ldg(bhh + n);
                    float gf  = c[1][mf][nf][i] + __ldg(bih + 1024 + n) + __ldg(bhh + 1024 + n);
                    float gc  = c[2][mf][nf][i] + __ldg(bih + 2048 + n) + __ldg(bhh + 2048 + n);
                    float go  = c[3][mf][nf][i] + __ldg(bih + 3072 + n) + __ldg(bhh + 3072 + n);
                    float gia = c[4][mf][nf][i] + __ldg(batt + n);
                    float gaa = c[5][mf][nf][i] + __ldg(batt + 1024 + n);
                    float i_  = sigmf(gi);
                    float f_  = sigmf(gf);
                    float c_  = tanhf(gc);
                    float o_  = sigmf(go);
                    float ia_ = sigmf(gia);
                    float aa_ = tanhf(gaa);
                    float cv  = f_ * ((q == 0) ? cx2.x : cx2.y) + i_ * c_ + ia_ * aa_;
                    cyv[q] = cv;
                    hyv[q] = o_ * tanhf(cv);
                }
                *(float2*)(out + (size_t)row * HDIM + col)           = make_float2(hyv[0], hyv[1]);
                *(float2*)(out + cy_base + (size_t)row * HDIM + col) = make_float2(cyv[0], cyv[1]);
            }
        }
    }
}

extern "C" void kernel_launch(void* const* d_in, const int* in_sizes, int n_in,
                              void* d_out, int out_size)
{
    (void)in_sizes; (void)n_in; (void)out_size;
    const float* inp  = (const float*)d_in[0];
    const float* hx   = (const float*)d_in[1];
    const float* cx   = (const float*)d_in[2];
    const float* att  = (const float*)d_in[3];
    const float* wih  = (const float*)d_in[4];
    const float* whh  = (const float*)d_in[5];
    const float* bih  = (const float*)d_in[6];
    const float* bhh  = (const float*)d_in[7];
    const float* watt = (const float*)d_in[8];
    const float* batt = (const float*)d_in[9];
    float* out = (float*)d_out;

    dim3 cgrid(1024, 6);
    cvt_all_kernel<<<cgrid, 256>>>((const float4*)inp, (const float4*)hx,
                                   (const float4*)att, (const float4*)wih,
                                   (const float4*)whh, (const float4*)watt);

    cudaFuncSetAttribute(lstm_att_kernel,
                         cudaFuncAttributeMaxDynamicSharedMemorySize, SMEMB);
    dim3 grid(HDIM / BN, BATCH / BM);  // n-tiles fastest => A/L2 reuse within a wave
    lstm_att_kernel<<<grid, NTH, SMEMB>>>(cx, bih, bhh, batt, out);
}

// round 6
// speedup vs baseline: 1.4925x; 1.1381x over previous
#include <cuda_runtime.h>
#include <cstdint>

#define DI __device__ __forceinline__

static constexpr int HDIM   = 1024;
static constexpr int BATCH  = 8192;
static constexpr int BM     = 128;   // batch rows per CTA
static constexpr int BN     = 32;    // gate cols per CTA (x6 gate blocks)
static constexpr int NTH    = 256;   // 8 warps: 4 (m) x 2 (n)
static constexpr int NSTAGE = 96;    // 32 input + 32 hx + 32 att K-stages
static constexpr int RING   = 3;     // 3-deep ring -> 96KB -> 2 CTAs/SM

// stage buffer: A 128x32 tf32 (16KB) + B 4x32x32 (16KB)
static constexpr int ABYTES = BM * 128;        // 16384
static constexpr int BUFB   = ABYTES + 16384;  // 32768
static constexpr int SMEMB  = RING * BUFB;     // 98304

// tf32-converted scratch (prepass output). Offsets in u32 elements.
static constexpr size_t OFF_INP  = 0;
static constexpr size_t OFF_HX   = 8388608;
static constexpr size_t OFF_ATT  = 16777216;
static constexpr size_t OFF_WIH  = 25165824;
static constexpr size_t OFF_WHH  = 29360128;
static constexpr size_t OFF_WATT = 33554432;
static constexpr size_t CVT_TOTAL = 35651584;   // ~142.6 MB

__device__ uint32_t g_cvt[CVT_TOTAL];

DI uint32_t f2tf(float x) {  // round-to-nearest tf32 (unbiased)
    uint32_t r;
    asm("cvt.rna.tf32.f32 %0, %1;" : "=r"(r) : "f"(x));
    return r;
}
DI float sigmf(float x) { return 1.0f / (1.0f + __expf(-x)); }

DI uint32_t smem_u32(const void* p) {
    uint32_t r;
    asm("{ .reg .u64 t; cvta.to.shared.u64 t, %1; cvt.u32.u64 %0, t; }" : "=r"(r) : "l"(p));
    return r;
}
DI void cp16(uint32_t sdst, const uint32_t* gsrc) {
    asm volatile("cp.async.cg.shared.global [%0], [%1], 16;" :: "r"(sdst), "l"(gsrc));
}
DI void cp_commit() { asm volatile("cp.async.commit_group;" ::: "memory"); }
template <int N>
DI void cp_wait() { asm volatile("cp.async.wait_group %0;" :: "n"(N) : "memory"); }

DI void ldsm4(uint32_t* r, uint32_t addr) {
    asm volatile("ldmatrix.sync.aligned.m8n8.x4.shared.b16 {%0,%1,%2,%3}, [%4];"
                 : "=r"(r[0]), "=r"(r[1]), "=r"(r[2]), "=r"(r[3]) : "r"(addr));
}
DI void mma8(float* d, const uint32_t* a, const uint32_t* b) {
    asm volatile(
        "mma.sync.aligned.m16n8k8.row.col.f32.tf32.tf32.f32 "
        "{%0,%1,%2,%3}, {%4,%5,%6,%7}, {%8,%9}, {%0,%1,%2,%3};"
        : "+f"(d[0]), "+f"(d[1]), "+f"(d[2]), "+f"(d[3])
        : "r"(a[0]), "r"(a[1]), "r"(a[2]), "r"(a[3]), "r"(b[0]), "r"(b[1]));
}

// ---- prepass: single launch, fp32 -> tf32(RNA) bulk convert (6 segments) ----
__global__ void cvt_all_kernel(const float4* s0, const float4* s1, const float4* s2,
                               const float4* s3, const float4* s4, const float4* s5)
{
    const int seg = blockIdx.y;
    const float4* src;
    uint4* dst;
    int n4;
    uint32_t* g = g_cvt;
    switch (seg) {
        case 0: src = s0; dst = (uint4*)(g + OFF_INP);  n4 = 2097152; break;
        case 1: src = s1; dst = (uint4*)(g + OFF_HX);   n4 = 2097152; break;
        case 2: src = s2; dst = (uint4*)(g + OFF_ATT);  n4 = 2097152; break;
        case 3: src = s3; dst = (uint4*)(g + OFF_WIH);  n4 = 1048576; break;
        case 4: src = s4; dst = (uint4*)(g + OFF_WHH);  n4 = 1048576; break;
        default: src = s5; dst = (uint4*)(g + OFF_WATT); n4 = 524288; break;
    }
    int i = blockIdx.x * blockDim.x + threadIdx.x;
    int stride = gridDim.x * blockDim.x;
    for (; i < n4; i += stride) {
        float4 v = __ldg(src + i);
        dst[i] = make_uint4(f2tf(v.x), f2tf(v.y), f2tf(v.z), f2tf(v.w));
    }
}

// ---- main kernel ----
// stages 0..31 : A=input, B=wih  (4 gate blocks, accum c[0..3])
// stages 32..63: A=hx,    B=whh  (4 gate blocks, accum c[0..3])
// stages 64..95: A=att,   B=watt (2 att blocks,  accum c[4..5])
DI void issue_stage(int s, uint32_t buf, uint32_t sA, uint32_t sB,
                    const uint32_t* Arow, const uint32_t* Brow)
{
    const int seg = s >> 5;
    const int k0  = (s & 31) << 5;
    // segment deltas: A +8388608/seg, B +4194304/seg (elements)
    const uint32_t* Ap = Arow + (size_t)seg * 8388608 + k0;
    const uint32_t* Bp = Brow + (size_t)seg * 4194304 + k0;
    const uint32_t dA = buf + sA;
    const uint32_t dB = buf + sB;
    cp16(dA,         Ap);
    cp16(dA + 4096,  Ap + 32768);
    cp16(dA + 8192,  Ap + 65536);
    cp16(dA + 12288, Ap + 98304);
    cp16(dB,         Bp);
    cp16(dB + 4096,  Bp + 1048576);
    if (seg != 2) {
        cp16(dB + 8192,  Bp + 2097152);
        cp16(dB + 12288, Bp + 3145728);
    }
    cp_commit();
}

template <int NB, int CB>
DI void compute_stage(uint32_t buf, uint32_t pA0, uint32_t pA1, uint32_t pB,
                      float c[6][2][2][4])
{
    const uint32_t aA0 = buf + pA0;
    const uint32_t aA1 = buf + pA1;
    const uint32_t bB  = buf + pB;
    #pragma unroll
    for (int k8 = 0; k8 < 4; ++k8) {
        const uint32_t kx = (uint32_t)(k8 << 5);   // immediate XOR per k8
        uint32_t a0[4], a1[4];
        ldsm4(a0, aA0 ^ kx);
        ldsm4(a1, aA1 ^ kx);
        #pragma unroll
        for (int blk = 0; blk < NB; ++blk) {
            uint32_t b[4];
            ldsm4(b, (bB + blk * 4096) ^ kx);
            mma8(c[CB + blk][0][0], a0, b);
            mma8(c[CB + blk][0][1], a0, b + 2);
            mma8(c[CB + blk][1][0], a1, b);
            mma8(c[CB + blk][1][1], a1, b + 2);
        }
    }
}

__global__ __launch_bounds__(NTH, 2)
void lstm_att_kernel(const float* __restrict__ cx,
                     const float* __restrict__ bih, const float* __restrict__ bhh,
                     const float* __restrict__ batt,
                     float* __restrict__ out)
{
    extern __shared__ char smem[];
    const int tid  = threadIdx.x;
    const int wid  = tid >> 5;
    const int lane = tid & 31;
    const int wm = wid >> 1, wn = wid & 1;
    const int n0 = blockIdx.x * BN;
    const int m0 = blockIdx.y * BM;
    const uint32_t sbase = smem_u32(smem);

    // ---- loop-invariant producer addressing (NTH=256: blk == j-unroll index) ----
    const int tid8 = tid >> 3;           // 0..31 row within 32-row chunk
    const int cc   = tid & 7;            // 16B column
    const uint32_t sw   = (uint32_t)((cc ^ (tid8 & 7)) << 4);
    const uint32_t sAof = (uint32_t)(tid8 * 128) + sw;            // A dst offset in buf
    const uint32_t sBof = (uint32_t)ABYTES + (uint32_t)(tid8 * 128) + sw;
    const uint32_t* Arow = g_cvt + OFF_INP + (size_t)(m0 + tid8) * HDIM + cc * 4;
    const uint32_t* Brow = g_cvt + OFF_WIH + (size_t)(n0 + tid8) * HDIM + cc * 4;

    // ---- loop-invariant consumer (ldsm) addressing, XOR-folded ----
    const int rowA = wm * 32 + (lane & 15);
    const int ahi  = (lane >> 4) & 1;
    const int ax   = rowA & 7;
    const uint32_t pA0 = (uint32_t)(rowA * 128)        ^ (uint32_t)(((ahi ^ ax) & 7) << 4);
    const uint32_t pA1 = (uint32_t)((rowA + 16) * 128) ^ (uint32_t)(((ahi ^ ax) & 7) << 4);
    const int rowB = wn * 16 + (lane & 7) + ((lane & 16) >> 1);
    const int bhi  = (lane >> 3) & 1;
    const int bx   = rowB & 7;
    const uint32_t pB  = (uint32_t)ABYTES + ((uint32_t)(rowB * 128) ^ (uint32_t)(((bhi ^ bx) & 7) << 4));

    float c[6][2][2][4];
    #pragma unroll
    for (int b = 0; b < 6; ++b)
        #pragma unroll
        for (int mf = 0; mf < 2; ++mf)
            #pragma unroll
            for (int nf = 0; nf < 2; ++nf)
                #pragma unroll
                for (int i = 0; i < 4; ++i) c[b][mf][nf][i] = 0.0f;

    issue_stage(0, sbase,            sAof, sBof, Arow, Brow);
    issue_stage(1, sbase + BUFB,     sAof, sBof, Arow, Brow);

    int ring_c = 0;          // slot of stage s
    int ring_i = 2;          // slot of stage s+2
    for (int s = 0; s < NSTAGE; ++s) {
        cp_wait<1>();
        __syncthreads();
        if (s + 2 < NSTAGE)
            issue_stage(s + 2, sbase + ring_i * BUFB, sAof, sBof, Arow, Brow);
        else
            cp_commit();     // keep group accounting so wait<1> retires stage s+1
        const uint32_t buf = sbase + ring_c * BUFB;
        if (s < 64) compute_stage<4, 0>(buf, pA0, pA1, pB, c);
        else        compute_stage<2, 4>(buf, pA0, pA1, pB, c);
        ring_c = (ring_c == RING - 1) ? 0 : ring_c + 1;
        ring_i = (ring_i == RING - 1) ? 0 : ring_i + 1;
    }

    // ---- fused LSTM epilogue: all 6 gates for (row,col) live in this thread ----
    const int gid = lane >> 2, tig = lane & 3;
    const size_t cy_base = (size_t)BATCH * HDIM;
    #pragma unroll
    for (int mf = 0; mf < 2; ++mf) {
        #pragma unroll
        for (int i2 = 0; i2 < 2; ++i2) {
            const int row = m0 + wm * 32 + mf * 16 + gid + i2 * 8;
            #pragma unroll
            for (int nf = 0; nf < 2; ++nf) {
                const int col = n0 + wn * 16 + nf * 8 + tig * 2;
                float2 cx2 = __ldg((const float2*)(cx + (size_t)row * HDIM + col));
                float hyv[2], cyv[2];
                #pragma unroll
                for (int q = 0; q < 2; ++q) {
                    const int i = i2 * 2 + q;
                    const int n = col + q;
                    float gi  = c[0][mf][nf][i] + __ldg(bih + n)        + __ldg(bhh + n);
                    float gf  = c[1][mf][nf][i] + __ldg(bih + 1024 + n) + __ldg(bhh + 1024 + n);
                    float gc  = c[2][mf][nf][i] + __ldg(bih + 2048 + n) + __ldg(bhh + 2048 + n);
                    float go  = c[3][mf][nf][i] + __ldg(bih + 3072 + n) + __ldg(bhh + 3072 + n);
                    float gia = c[4][mf][nf][i] + __ldg(batt + n);
                    float gaa = c[5][mf][nf][i] + __ldg(batt + 1024 + n);
                    float i_  = sigmf(gi);
                    float f_  = sigmf(gf);
                    float c_  = tanhf(gc);
                    float o_  = sigmf(go);
                    float ia_ = sigmf(gia);
                    float aa_ = tanhf(gaa);
                    float cv  = f_ * ((q == 0) ? cx2.x : cx2.y) + i_ * c_ + ia_ * aa_;
                    cyv[q] = cv;
                    hyv[q] = o_ * tanhf(cv);
                }
                *(float2*)(out + (size_t)row * HDIM + col)           = make_float2(hyv[0], hyv[1]);
                *(float2*)(out + cy_base + (size_t)row * HDIM + col) = make_float2(cyv[0], cyv[1]);
            }
        }
    }
}

extern "C" void kernel_launch(void* const* d_in, const int* in_sizes, int n_in,
                              void* d_out, int out_size)
{
    (void)in_sizes; (void)n_in; (void)out_size;
    const float* inp  = (const float*)d_in[0];
    const float* hx   = (const float*)d_in[1];
    const float* cx   = (const float*)d_in[2];
    const float* att  = (const float*)d_in[3];
    const float* wih  = (const float*)d_in[4];
    const float* whh  = (const float*)d_in[5];
    const float* bih  = (const float*)d_in[6];
    const float* bhh  = (const float*)d_in[7];
    const float* watt = (const float*)d_in[8];
    const float* batt = (const float*)d_in[9];
    float* out = (float*)d_out;

    dim3 cgrid(1024, 6);
    cvt_all_kernel<<<cgrid, 256>>>((const float4*)inp, (const float4*)hx,
                                   (const float4*)att, (const float4*)wih,
                                   (const float4*)whh, (const float4*)watt);

    cudaFuncSetAttribute(lstm_att_kernel,
                         cudaFuncAttributeMaxDynamicSharedMemorySize, SMEMB);
    dim3 grid(HDIM / BN, BATCH / BM);  // n-tiles fastest => A/L2 reuse within a wave
    lstm_att_kernel<<<grid, NTH, SMEMB>>>(cx, bih, bhh, batt, out);
}